// round 11
// baseline (speedup 1.0000x reference)
#include <cuda_runtime.h>
#include <cuda_bf16.h>
#include <math.h>
#include <stdint.h>

#define NB 32768
#define NT (NB*4)              // 131072 tokens
#define QK_SCALE 0.17677669529663687f

// ---------------- scratch (static device globals) ---------------------------
__device__ __align__(16) __nv_bfloat16 g_Wqk[(size_t)512 * 256]; // [Q|K] rows, hi
__device__ __align__(16) __nv_bfloat16 g_Wvr[(size_t)512 * 256]; // interleaved [V_f;R_f]
__device__ __align__(16) __nv_bfloat16 g_Wo1[(size_t)256 * 256]; // Wo hi
__device__ __align__(16) __nv_bfloat16 g_Pbf[(size_t)NT * 512];  // [Q|K] bf16, 134 MB
__device__ __align__(16) __nv_bfloat16 g_Veff[(size_t)NT * 256]; // sigmoid(R)*V bf16

// ---------------- PTX helpers ------------------------------------------------
__device__ __forceinline__ uint32_t smem_u32(const void* p) {
    uint32_t a;
    asm("{ .reg .u64 t; cvta.to.shared.u64 t, %1; cvt.u32.u64 %0, t; }" : "=r"(a) : "l"(p));
    return a;
}
__device__ __forceinline__ void cp16(uint32_t dst, const void* src) {
    asm volatile("cp.async.cg.shared.global [%0], [%1], 16;" :: "r"(dst), "l"(src) : "memory");
}
__device__ __forceinline__ void cp_commit() {
    asm volatile("cp.async.commit_group;" ::: "memory");
}
__device__ __forceinline__ void cp_wait1() {
    asm volatile("cp.async.wait_group 1;" ::: "memory");
}
__device__ __forceinline__ void ldm_x4(uint32_t* r, uint32_t addr) {
    asm volatile("ldmatrix.sync.aligned.m8n8.x4.shared.b16 {%0,%1,%2,%3}, [%4];"
                 : "=r"(r[0]), "=r"(r[1]), "=r"(r[2]), "=r"(r[3]) : "r"(addr));
}
__device__ __forceinline__ void mma16816(float* c, const uint32_t* a, uint32_t b0, uint32_t b1) {
    asm volatile(
        "mma.sync.aligned.m16n8k16.row.col.f32.bf16.bf16.f32 "
        "{%0,%1,%2,%3}, {%4,%5,%6,%7}, {%8,%9}, {%0,%1,%2,%3};"
        : "+f"(c[0]), "+f"(c[1]), "+f"(c[2]), "+f"(c[3])
        : "r"(a[0]), "r"(a[1]), "r"(a[2]), "r"(a[3]), "r"(b0), "r"(b1));
}

struct __align__(8) bf4 { __nv_bfloat162 a, b; };           // 4 bf16
struct __align__(16) bf8 { __nv_bfloat162 a, b, c, d; };    // 8 bf16
__device__ __forceinline__ bf4 to_bf4(float4 v) {
    bf4 o;
    o.a = __halves2bfloat162(__float2bfloat16(v.x), __float2bfloat16(v.y));
    o.b = __halves2bfloat162(__float2bfloat16(v.z), __float2bfloat16(v.w));
    return o;
}
__device__ __forceinline__ uint4 pack_bf8(float4 v0, float4 v1) {
    bf8 o;
    o.a = __halves2bfloat162(__float2bfloat16(v0.x), __float2bfloat16(v0.y));
    o.b = __halves2bfloat162(__float2bfloat16(v0.z), __float2bfloat16(v0.w));
    o.c = __halves2bfloat162(__float2bfloat16(v1.x), __float2bfloat16(v1.y));
    o.d = __halves2bfloat162(__float2bfloat16(v1.z), __float2bfloat16(v1.w));
    return *(uint4*)&o;
}

// ============================================================================
// weight conversion (tiny)
// ============================================================================
__global__ __launch_bounds__(256)
void k_convW(const float* __restrict__ Wq, const float* __restrict__ Wk,
             const float* __restrict__ Wv, const float* __restrict__ Wr,
             const float* __restrict__ Wo) {
    long idx = (long)blockIdx.x * 256 + threadIdx.x;   // 1280*64 items
    int j = (int)(idx >> 6); int col = (int)(idx & 63) * 4;
    if (j < 512) {
        const float* src = ((j < 256) ? Wq : Wk) + (size_t)(j & 255) * 256;
        float4 v = *(const float4*)(src + col);
        *(bf4*)(g_Wqk + (size_t)j * 256 + col) = to_bf4(v);
    } else if (j < 1024) {
        int f = j & 255;
        bool isR = (j >= 768);
        const float* src = (isR ? Wr : Wv) + (size_t)f * 256;
        float4 v = *(const float4*)(src + col);
        *(bf4*)(g_Wvr + (size_t)(2 * f + (isR ? 1 : 0)) * 256 + col) = to_bf4(v);
    } else {
        float4 v = *(const float4*)(Wo + (size_t)(j - 1024) * 256 + col);
        *(bf4*)(g_Wo1 + (size_t)(j - 1024) * 256 + col) = to_bf4(v);
    }
}

// ---------------- shared tile helpers (64 bf16 = 8x16B chunks per row) -------
__device__ __forceinline__ uint32_t sw_off(int r, int c) {      // bytes
    return (uint32_t)((r * 8 + (c ^ (r & 7))) * 16);
}

// ============================================================================
// GEMM1 with fused X conversion: A loaded as f32 via LDG (register prefetch),
// converted to bf16 in-flight, STS into 2 swizzled A-buffers.
// B (weights, bf16) via 3-stage cp.async.
// bx<4: QK -> g_Pbf[NT,512] bf16; bx>=4: VR -> g_Veff (sigmoid-gated)
// CTA 128x128, 8 warps (32x64), K=256 in 4 chunks.
// smem: A 2x16KB @0, B 3x16KB @32768; epilogue staging reuses from 0.
// ============================================================================
#define G1_B0 32768
#define G1_SMEM (32768 + 49152)    // 80 KB
#define VSTRIDE 80
#define QSTRIDE 136

__global__ void __launch_bounds__(256, 2) k_gemm1(const float* __restrict__ X) {
    extern __shared__ __align__(1024) char smem[];
    const uint32_t sb = smem_u32(smem);
    const int tid = threadIdx.x;
    const int l = tid & 31, w = tid >> 5;
    const int wm = w & 3, wn = w >> 2;
    const int bx = blockIdx.x;
    const bool qk = (bx < 4);
    const int nloc = (qk ? bx : bx - 4) * 128;
    const size_t row0 = (size_t)blockIdx.y * 128;

    const int lr = tid >> 3, lc = tid & 7;
    const __nv_bfloat16* wbase = qk ? g_Wqk : g_Wvr;

    float acc[2][8][4];
#pragma unroll
    for (int i = 0; i < 2; i++)
#pragma unroll
        for (int j = 0; j < 8; j++)
#pragma unroll
            for (int k = 0; k < 4; k++) acc[i][j][k] = 0.f;

    // ---- A prefetch: LDG f32, convert to bf16, hold in regs ----
    uint4 apf[4];
    auto ldgA = [&](int s) {
        const int acol = s * 64;
#pragma unroll
        for (int u = 0; u < 4; u++) {
            int r = lr + u * 32;
            const float* p = X + (row0 + r) * 256 + acol + lc * 8;
            float4 v0 = *(const float4*)p;
            float4 v1 = *(const float4*)(p + 4);
            apf[u] = pack_bf8(v0, v1);
        }
    };
    auto stsA = [&](int buf) {
        const uint32_t sa = sb + buf * 16384;
#pragma unroll
        for (int u = 0; u < 4; u++) {
            int r = lr + u * 32;
            *(uint4*)(smem + buf * 16384 + sw_off(r, lc)) = apf[u];
        }
        (void)sa;
    };
    auto issueB = [&](int s, int buf) {
        const uint32_t sbm = sb + G1_B0 + buf * 16384;
        const int acol = s * 64;
#pragma unroll
        for (int u = 0; u < 4; u++) {
            int r = lr + u * 32;
            cp16(sbm + sw_off(r, lc), wbase + (size_t)(nloc + r) * 256 + acol + lc * 8);
        }
    };

    ldgA(0);
    issueB(0, 0); cp_commit();
    issueB(1, 1); cp_commit();

    for (int s = 0; s < 4; s++) {
        stsA(s & 1);
        if (s + 1 < 4) ldgA(s + 1);                       // overlap with compute(s)
        if (s + 2 < 4) { issueB(s + 2, (s + 2) % 3); cp_commit(); }
        else           { cp_commit(); }
        cp_wait1();                                        // B(s) resident
        __syncthreads();

        const uint32_t sa  = sb + (s & 1) * 16384;
        const uint32_t sbm = sb + G1_B0 + (s % 3) * 16384;
#pragma unroll
        for (int ks = 0; ks < 4; ks++) {
            uint32_t a[2][4], b[4][4];
            const int cc = ks * 2 + (l >> 4);
#pragma unroll
            for (int mi = 0; mi < 2; mi++) {
                int r = wm * 32 + mi * 16 + (l & 15);
                ldm_x4(a[mi], sa + sw_off(r, cc));
            }
#pragma unroll
            for (int ni = 0; ni < 4; ni++) {
                int r = wn * 64 + ni * 16 + (l & 15);
                ldm_x4(b[ni], sbm + sw_off(r, cc));
            }
#pragma unroll
            for (int mi = 0; mi < 2; mi++)
#pragma unroll
                for (int ni = 0; ni < 4; ni++) {
                    mma16816(acc[mi][ni * 2],     a[mi], b[ni][0], b[ni][2]);
                    mma16816(acc[mi][ni * 2 + 1], a[mi], b[ni][1], b[ni][3]);
                }
        }
        __syncthreads();                                   // A-buffer WAR hazard
    }

    if (qk) {
        __nv_bfloat16* sv = (__nv_bfloat16*)smem;    // [128][QSTRIDE]
#pragma unroll
        for (int mi = 0; mi < 2; mi++) {
            int rloc = wm * 32 + mi * 16 + (l >> 2);
#pragma unroll
            for (int ni = 0; ni < 8; ni++) {
                int cl = wn * 64 + ni * 8 + (l & 3) * 2;
                *(__nv_bfloat162*)(sv + rloc * QSTRIDE + cl) =
                    __halves2bfloat162(__float2bfloat16(acc[mi][ni][0]),
                                       __float2bfloat16(acc[mi][ni][1]));
                *(__nv_bfloat162*)(sv + (rloc + 8) * QSTRIDE + cl) =
                    __halves2bfloat162(__float2bfloat16(acc[mi][ni][2]),
                                       __float2bfloat16(acc[mi][ni][3]));
            }
        }
        __syncthreads();
        const int rr = tid >> 4;          // 0..15
        const int cc8 = (tid & 15) * 8;   // 0..120
#pragma unroll
        for (int it = 0; it < 8; it++) {
            int r = it * 16 + rr;
            *(uint4*)(g_Pbf + (row0 + r) * 512 + nloc + cc8) =
                *(const uint4*)(sv + r * QSTRIDE + cc8);
        }
    } else {
        __nv_bfloat16* sv = (__nv_bfloat16*)smem;    // [128][VSTRIDE]
#pragma unroll
        for (int mi = 0; mi < 2; mi++) {
            int rloc = wm * 32 + mi * 16 + (l >> 2);
#pragma unroll
            for (int ni = 0; ni < 8; ni++) {
                int fl = wn * 32 + ni * 4 + (l & 3);
                float ve0 = acc[mi][ni][0] / (1.f + __expf(-acc[mi][ni][1]));
                float ve1 = acc[mi][ni][2] / (1.f + __expf(-acc[mi][ni][3]));
                sv[rloc * VSTRIDE + fl]       = __float2bfloat16(ve0);
                sv[(rloc + 8) * VSTRIDE + fl] = __float2bfloat16(ve1);
            }
        }
        __syncthreads();
        const int rr = tid >> 3;
        const int cc8 = (tid & 7) * 8;
        const int fbase = nloc / 2;
#pragma unroll
        for (int it = 0; it < 4; it++) {
            int r = it * 32 + rr;
            *(uint4*)(g_Veff + (row0 + r) * 256 + fbase + cc8) =
                *(const uint4*)(sv + r * VSTRIDE + cc8);
        }
    }
}

// ============================================================================
// FUSED attention + GEMM2 + residual + LN. Q,K bf16 in g_Pbf. (unchanged)
// ============================================================================
#define APAD 36
#define SM_AHI 0
#define SM_STAGE 32768
#define G2F_SMEM (32768 + 73728)

__global__ void __launch_bounds__(256, 2)
k_attn_gemm2(const float* __restrict__ tok, const float* __restrict__ gma,
             const float* __restrict__ bta, float* __restrict__ Y,
             float* __restrict__ attn_out)
{
    extern __shared__ __align__(1024) char smem[];
    const uint32_t sb = smem_u32(smem);
    const int tid = threadIdx.x;
    const int l = tid & 31, w = tid >> 5;
    const size_t row0 = (size_t)blockIdx.x * 64;

    // ======================= Phase A: attention =============================
    {
        float* sK = (float*)(smem + SM_STAGE + w * 9216);
        float* sV = sK + 4 * (8 * APAD);
        const int i = l >> 3;
        const int h = l & 7;

#pragma unroll
        for (int batch = 0; batch < 2; batch++) {
            const int sl = batch * 8 + w;
            const size_t rowb = row0 + (size_t)sl * 4;

#pragma unroll
            for (int ii = 0; ii < 4; ii++) {
                int ov = l * 8, hv = ov >> 5, dv = ov & 31;
                bf8 kv = *((const bf8*)(g_Pbf + (rowb + ii) * 512 + 256) + l);
                float2 k0 = __bfloat1622float2(kv.a), k1 = __bfloat1622float2(kv.b);
                float2 k2 = __bfloat1622float2(kv.c), k3 = __bfloat1622float2(kv.d);
                *(float4*)(sK + (ii * 8 + hv) * APAD + dv)     = make_float4(k0.x, k0.y, k1.x, k1.y);
                *(float4*)(sK + (ii * 8 + hv) * APAD + dv + 4) = make_float4(k2.x, k2.y, k3.x, k3.y);

                bf8 vv = *((const bf8*)(g_Veff + (rowb + ii) * 256) + l);
                float2 p0 = __bfloat1622float2(vv.a), p1 = __bfloat1622float2(vv.b);
                float2 p2 = __bfloat1622float2(vv.c), p3 = __bfloat1622float2(vv.d);
                *(float4*)(sV + (ii * 8 + hv) * APAD + dv)     = make_float4(p0.x, p0.y, p1.x, p1.y);
                *(float4*)(sV + (ii * 8 + hv) * APAD + dv + 4) = make_float4(p2.x, p2.y, p3.x, p3.y);
            }
            __syncwarp();

            const size_t t = rowb + i;
            float4 Q[8];
            {
                const bf8* qp = (const bf8*)(g_Pbf + t * 512 + h * 32);
#pragma unroll
                for (int c = 0; c < 4; c++) {
                    bf8 qv = qp[c];
                    float2 a0 = __bfloat1622float2(qv.a), a1 = __bfloat1622float2(qv.b);
                    float2 a2 = __bfloat1622float2(qv.c), a3 = __bfloat1622float2(qv.d);
                    Q[c * 2]     = make_float4(a0.x, a0.y, a1.x, a1.y);
                    Q[c * 2 + 1] = make_float4(a2.x, a2.y, a3.x, a3.y);
                }
            }

            float s[3];
#pragma unroll
            for (int lix = 0; lix < 3; lix++) {
                int nb = (lix >= i) ? lix + 1 : lix;
                const float* kp = sK + (nb * 8 + h) * APAD;
                float a0 = 0.f, a1 = 0.f;
#pragma unroll
                for (int c = 0; c < 4; c++) {
                    float4 k0 = *(const float4*)(kp + c * 8);
                    float4 k1 = *(const float4*)(kp + c * 8 + 4);
                    float4 q0 = Q[c * 2], q1 = Q[c * 2 + 1];
                    a0 = fmaf(q0.x, k0.x, a0); a0 = fmaf(q0.y, k0.y, a0);
                    a0 = fmaf(q0.z, k0.z, a0); a0 = fmaf(q0.w, k0.w, a0);
                    a1 = fmaf(q1.x, k1.x, a1); a1 = fmaf(q1.y, k1.y, a1);
                    a1 = fmaf(q1.z, k1.z, a1); a1 = fmaf(q1.w, k1.w, a1);
                }
                s[lix] = (a0 + a1) * QK_SCALE;
            }

            float m = fmaxf(s[0], fmaxf(s[1], s[2]));
            float e0 = __expf(s[0] - m), e1 = __expf(s[1] - m), e2 = __expf(s[2] - m);
            float inv = 1.f / (e0 + e1 + e2);
            float a[3] = { e0 * inv, e1 * inv, e2 * inv };

            size_t ao = (t * 8 + h) * 3;
            attn_out[ao + 0] = a[0]; attn_out[ao + 1] = a[1]; attn_out[ao + 2] = a[2];

            float O[32];
#pragma unroll
            for (int d = 0; d < 32; d++) O[d] = 0.f;
#pragma unroll
            for (int lix = 0; lix < 3; lix++) {
                int nb = (lix >= i) ? lix + 1 : lix;
                const float* vp = sV + (nb * 8 + h) * APAD;
                float al = a[lix];
#pragma unroll
                for (int c = 0; c < 8; c++) {
                    float4 v = *(const float4*)(vp + c * 4);
                    O[c*4+0] = fmaf(al, v.x, O[c*4+0]);
                    O[c*4+1] = fmaf(al, v.y, O[c*4+1]);
                    O[c*4+2] = fmaf(al, v.z, O[c*4+2]);
                    O[c*4+3] = fmaf(al, v.w, O[c*4+3]);
                }
            }

            const int arow = sl * 4 + i;
#pragma unroll
            for (int j = 0; j < 4; j++) {
                int col = h * 32 + j * 8;
                int kblk = col >> 6;
                int cw = (col & 63) >> 3;
                bf4 lo8 = to_bf4(make_float4(O[j*8+0], O[j*8+1], O[j*8+2], O[j*8+3]));
                bf4 hi8 = to_bf4(make_float4(O[j*8+4], O[j*8+5], O[j*8+6], O[j*8+7]));
                char* dst = smem + SM_AHI + kblk * 8192 + sw_off(arow, cw);
                *(bf4*)dst       = lo8;
                *(bf4*)(dst + 8) = hi8;
            }
            __syncwarp();
        }
    }
    __syncthreads();

    // ======================= Phase B: Wo GEMM ===============================
    const int wm = w & 1, wn = w >> 1;
    const int lr = tid >> 3, lc = tid & 7;

    float acc[2][8][4];
#pragma unroll
    for (int i = 0; i < 2; i++)
#pragma unroll
        for (int j = 0; j < 8; j++)
#pragma unroll
            for (int k = 0; k < 4; k++) acc[i][j][k] = 0.f;

    auto issueB = [&](int s, int buf) {
        const int k0 = s * 64;
        const uint32_t sbm = sb + SM_STAGE + buf * 32768;
#pragma unroll
        for (int u = 0; u < 8; u++) {
            int r = lr + u * 32;
            cp16(sbm + sw_off(r, lc), g_Wo1 + (size_t)r * 256 + k0 + lc * 8);
        }
    };

    issueB(0, 0); cp_commit();

    for (int s = 0; s < 4; s++) {
        if (s + 1 < 4) issueB(s + 1, (s + 1) & 1);
        cp_commit();
        cp_wait1();
        __syncthreads();

        const uint32_t sa  = sb + SM_AHI + s * 8192;
        const uint32_t sbm = sb + SM_STAGE + (s & 1) * 32768;
#pragma unroll
        for (int ks = 0; ks < 4; ks++) {
            uint32_t a[2][4], b[4][4];
            const int cc = ks * 2 + (l >> 4);
#pragma unroll
            for (int mi = 0; mi < 2; mi++) {
                int r = wm * 32 + mi * 16 + (l & 15);
                ldm_x4(a[mi], sa + sw_off(r, cc));
            }
#pragma unroll
            for (int ni = 0; ni < 4; ni++) {
                int r = wn * 64 + ni * 16 + (l & 15);
                ldm_x4(b[ni], sbm + sw_off(r, cc));
            }
#pragma unroll
            for (int mi = 0; mi < 2; mi++)
#pragma unroll
                for (int ni = 0; ni < 4; ni++) {
                    mma16816(acc[mi][ni * 2],     a[mi], b[ni][0], b[ni][2]);
                    mma16816(acc[mi][ni * 2 + 1], a[mi], b[ni][1], b[ni][3]);
                }
        }
        __syncthreads();
    }

    // ======================= Phase C: residual + LN =========================
    float* sred = (float*)(smem + SM_STAGE);
#pragma unroll
    for (int mi = 0; mi < 2; mi++) {
        int rb = wm * 32 + mi * 16 + (l >> 2);
#pragma unroll
        for (int ni = 0; ni < 8; ni++) {
            int col = wn * 64 + ni * 8 + (l & 3) * 2;
            *(float2*)(sred + rb * 260 + col) = make_float2(acc[mi][ni][0], acc[mi][ni][1]);
            *(float2*)(sred + (rb + 8) * 260 + col) = make_float2(acc[mi][ni][2], acc[mi][ni][3]);
        }
    }
    __syncthreads();

#pragma unroll
    for (int rr = 0; rr < 8; rr++) {
        int row = w * 8 + rr;
        size_t grow = row0 + row;
        float v[8];
        float4 t0 = *(const float4*)(tok + grow * 256 + l * 8);
        float4 t1 = *(const float4*)(tok + grow * 256 + l * 8 + 4);
        float4 s0 = *(const float4*)(sred + row * 260 + l * 8);
        float4 s1 = *(const float4*)(sred + row * 260 + l * 8 + 4);
        v[0] = s0.x + t0.x; v[1] = s0.y + t0.y; v[2] = s0.z + t0.z; v[3] = s0.w + t0.w;
        v[4] = s1.x + t1.x; v[5] = s1.y + t1.y; v[6] = s1.z + t1.z; v[7] = s1.w + t1.w;

        float sum = 0.f, sq = 0.f;
#pragma unroll
        for (int u = 0; u < 8; u++) { sum += v[u]; sq += v[u] * v[u]; }
#pragma unroll
        for (int off = 16; off >= 1; off >>= 1) {
            sum += __shfl_xor_sync(0xffffffffu, sum, off);
            sq  += __shfl_xor_sync(0xffffffffu, sq, off);
        }
        float mu = sum * (1.f / 256.f);
        float var = sq * (1.f / 256.f) - mu * mu;
        float is = rsqrtf(var + 1e-5f);

        float4 g0 = *(const float4*)(gma + l * 8);
        float4 g1 = *(const float4*)(gma + l * 8 + 4);
        float4 b0 = *(const float4*)(bta + l * 8);
        float4 b1 = *(const float4*)(bta + l * 8 + 4);
        *(float4*)(Y + grow * 256 + l * 8) = make_float4(
            (v[0]-mu)*is*g0.x + b0.x, (v[1]-mu)*is*g0.y + b0.y,
            (v[2]-mu)*is*g0.z + b0.z, (v[3]-mu)*is*g0.w + b0.w);
        *(float4*)(Y + grow * 256 + l * 8 + 4) = make_float4(
            (v[4]-mu)*is*g1.x + b1.x, (v[5]-mu)*is*g1.y + b1.y,
            (v[6]-mu)*is*g1.z + b1.z, (v[7]-mu)*is*g1.w + b1.w);
    }
}

// ============================================================================
extern "C" void kernel_launch(void* const* d_in, const int* in_sizes, int n_in,
                              void* d_out, int out_size)
{
    const float* tokens = (const float*)d_in[0];
    const float* Wq = (const float*)d_in[1];
    const float* Wk = (const float*)d_in[2];
    const float* Wv = (const float*)d_in[3];
    const float* Wr = (const float*)d_in[4];
    const float* Wo = (const float*)d_in[5];
    const float* ln_g = (const float*)d_in[6];
    const float* ln_b = (const float*)d_in[7];

    float* y = (float*)d_out;
    float* attn = y + (size_t)NT * 256;

    static int configured = 0;
    if (!configured) {
        cudaFuncSetAttribute(k_gemm1, cudaFuncAttributeMaxDynamicSharedMemorySize, G1_SMEM);
        cudaFuncSetAttribute(k_attn_gemm2, cudaFuncAttributeMaxDynamicSharedMemorySize, G2F_SMEM);
        configured = 1;
    }

    k_convW<<<1280 * 64 / 256, 256>>>(Wq, Wk, Wv, Wr, Wo);
    k_gemm1<<<dim3(8, 1024), 256, G1_SMEM>>>(tokens);
    k_attn_gemm2<<<NT / 64, 256, G2F_SMEM>>>(tokens, ln_g, ln_b, y, attn);
}

// round 13
// speedup vs baseline: 1.1406x; 1.1406x over previous
#include <cuda_runtime.h>
#include <cuda_bf16.h>
#include <math.h>
#include <stdint.h>

#define NB 32768
#define NT (NB*4)              // 131072 tokens
#define QK_SCALE 0.17677669529663687f

// ---------------- scratch (static device globals) ---------------------------
__device__ __align__(16) __nv_bfloat16 g_Xhi[(size_t)NT * 256];  // 67 MB (L2-resident)
__device__ __align__(16) __nv_bfloat16 g_Wqk[(size_t)512 * 256]; // [Q|K] rows, hi
__device__ __align__(16) __nv_bfloat16 g_Wvr[(size_t)512 * 256]; // interleaved [V_f;R_f]
__device__ __align__(16) __nv_bfloat16 g_Wo1[(size_t)256 * 256]; // Wo hi
__device__ __align__(16) __nv_bfloat16 g_Pbf[(size_t)NT * 512];  // [Q|K] bf16, 134 MB
__device__ __align__(16) __nv_bfloat16 g_Veff[(size_t)NT * 256]; // sigmoid(R)*V bf16

// ---------------- PTX helpers ------------------------------------------------
__device__ __forceinline__ uint32_t smem_u32(const void* p) {
    uint32_t a;
    asm("{ .reg .u64 t; cvta.to.shared.u64 t, %1; cvt.u32.u64 %0, t; }" : "=r"(a) : "l"(p));
    return a;
}
__device__ __forceinline__ void cp16(uint32_t dst, const void* src) {
    asm volatile("cp.async.cg.shared.global [%0], [%1], 16;" :: "r"(dst), "l"(src) : "memory");
}
__device__ __forceinline__ void cp8(uint32_t dst, const void* src) {
    asm volatile("cp.async.ca.shared.global [%0], [%1], 8;" :: "r"(dst), "l"(src) : "memory");
}
__device__ __forceinline__ void cp_commit() {
    asm volatile("cp.async.commit_group;" ::: "memory");
}
__device__ __forceinline__ void cp_wait1() {
    asm volatile("cp.async.wait_group 1;" ::: "memory");
}
__device__ __forceinline__ void cp_wait0() {
    asm volatile("cp.async.wait_group 0;" ::: "memory");
}
__device__ __forceinline__ void ldm_x4(uint32_t* r, uint32_t addr) {
    asm volatile("ldmatrix.sync.aligned.m8n8.x4.shared.b16 {%0,%1,%2,%3}, [%4];"
                 : "=r"(r[0]), "=r"(r[1]), "=r"(r[2]), "=r"(r[3]) : "r"(addr));
}
__device__ __forceinline__ void mma16816(float* c, const uint32_t* a, uint32_t b0, uint32_t b1) {
    asm volatile(
        "mma.sync.aligned.m16n8k16.row.col.f32.bf16.bf16.f32 "
        "{%0,%1,%2,%3}, {%4,%5,%6,%7}, {%8,%9}, {%0,%1,%2,%3};"
        : "+f"(c[0]), "+f"(c[1]), "+f"(c[2]), "+f"(c[3])
        : "r"(a[0]), "r"(a[1]), "r"(a[2]), "r"(a[3]), "r"(b0), "r"(b1));
}

struct __align__(8) bf4 { __nv_bfloat162 a, b; };           // 4 bf16
struct __align__(16) bf8 { __nv_bfloat162 a, b, c, d; };    // 8 bf16
__device__ __forceinline__ bf4 to_bf4(float4 v) {
    bf4 o;
    o.a = __halves2bfloat162(__float2bfloat16(v.x), __float2bfloat16(v.y));
    o.b = __halves2bfloat162(__float2bfloat16(v.z), __float2bfloat16(v.w));
    return o;
}
// unpack 4 bf16 (uint2) into one float4
__device__ __forceinline__ float4 bf4_unpack(uint2 u) {
    const bf4* p = (const bf4*)&u;
    float2 a = __bfloat1622float2(p->a), b = __bfloat1622float2(p->b);
    return make_float4(a.x, a.y, b.x, b.y);
}
// unpack 8 bf16 (uint4) into 2 float4
__device__ __forceinline__ void bf8_unpack(uint4 u, float4& lo, float4& hi) {
    const bf8* p = (const bf8*)&u;
    float2 a = __bfloat1622float2(p->a), b = __bfloat1622float2(p->b);
    float2 c = __bfloat1622float2(p->c), d = __bfloat1622float2(p->d);
    lo = make_float4(a.x, a.y, b.x, b.y);
    hi = make_float4(c.x, c.y, d.x, d.y);
}

// ============================================================================
// conversions (same as R10)
// ============================================================================
__global__ __launch_bounds__(256) void k_convX(const float* __restrict__ X) {
    long idx = (long)blockIdx.x * 256 + threadIdx.x;   // NT*64 items
    long t = idx >> 6; int col = (int)(idx & 63) * 4;
    float4 v = *(const float4*)(X + t * 256 + col);
    *(bf4*)(g_Xhi + t * 256 + col) = to_bf4(v);
}

__global__ __launch_bounds__(256)
void k_convW(const float* __restrict__ Wq, const float* __restrict__ Wk,
             const float* __restrict__ Wv, const float* __restrict__ Wr,
             const float* __restrict__ Wo) {
    long idx = (long)blockIdx.x * 256 + threadIdx.x;   // 1280*64 items
    int j = (int)(idx >> 6); int col = (int)(idx & 63) * 4;
    if (j < 512) {
        const float* src = ((j < 256) ? Wq : Wk) + (size_t)(j & 255) * 256;
        float4 v = *(const float4*)(src + col);
        *(bf4*)(g_Wqk + (size_t)j * 256 + col) = to_bf4(v);
    } else if (j < 1024) {
        int f = j & 255;
        bool isR = (j >= 768);
        const float* src = (isR ? Wr : Wv) + (size_t)f * 256;
        float4 v = *(const float4*)(src + col);
        *(bf4*)(g_Wvr + (size_t)(2 * f + (isR ? 1 : 0)) * 256 + col) = to_bf4(v);
    } else {
        float4 v = *(const float4*)(Wo + (size_t)(j - 1024) * 256 + col);
        *(bf4*)(g_Wo1 + (size_t)(j - 1024) * 256 + col) = to_bf4(v);
    }
}

// ---------------- shared tile helpers (64 bf16 = 8x16B chunks per row) -------
__device__ __forceinline__ uint32_t sw_off(int r, int c) {      // bytes
    return (uint32_t)((r * 8 + (c ^ (r & 7))) * 16);
}

// ============================================================================
// GEMM1 (R10 version): single-pass bf16, K=256 (4 chunks) for both slabs.
// bx<4: QK -> g_Pbf[NT,512] bf16; bx>=4: VR -> g_Veff (sigmoid-gated)
// CTA 128x128, 8 warps (32x64), 3-stage cp.async.
// ============================================================================
#define G1_STAGE 32768
#define G1_SMEM  (3 * G1_STAGE)
#define VSTRIDE 80
#define QSTRIDE 136

__global__ void __launch_bounds__(256, 2) k_gemm1() {
    extern __shared__ __align__(1024) char smem[];
    const uint32_t sb = smem_u32(smem);
    const int tid = threadIdx.x;
    const int l = tid & 31, w = tid >> 5;
    const int wm = w & 3, wn = w >> 2;
    const int bx = blockIdx.x;
    const bool qk = (bx < 4);
    const int nloc = (qk ? bx : bx - 4) * 128;
    const size_t row0 = (size_t)blockIdx.y * 128;

    const int lr = tid >> 3, lc = tid & 7;

    float acc[2][8][4];
#pragma unroll
    for (int i = 0; i < 2; i++)
#pragma unroll
        for (int j = 0; j < 8; j++)
#pragma unroll
            for (int k = 0; k < 4; k++) acc[i][j][k] = 0.f;

    const __nv_bfloat16* wbase = qk ? g_Wqk : g_Wvr;

    auto issue = [&](int s, int buf) {
        const uint32_t sa  = sb + buf * G1_STAGE;
        const uint32_t sbm = sa + 16384;
        const int acol = s * 64;
#pragma unroll
        for (int u = 0; u < 4; u++) {
            int r = lr + u * 32;
            cp16(sa + sw_off(r, lc), g_Xhi + (row0 + r) * 256 + acol + lc * 8);
        }
#pragma unroll
        for (int u = 0; u < 4; u++) {
            int r = lr + u * 32;
            cp16(sbm + sw_off(r, lc), wbase + (size_t)(nloc + r) * 256 + acol + lc * 8);
        }
    };

    issue(0, 0); cp_commit();
    issue(1, 1); cp_commit();

    int buf = 0;
    for (int s = 0; s < 4; s++) {
        cp_wait1();
        __syncthreads();
        if (s + 2 < 4) { issue(s + 2, (buf + 2) % 3); cp_commit(); }
        else           { cp_commit(); }

        const uint32_t sa  = sb + buf * G1_STAGE;
        const uint32_t sbm = sa + 16384;
#pragma unroll
        for (int ks = 0; ks < 4; ks++) {
            uint32_t a[2][4], b[4][4];
            const int cc = ks * 2 + (l >> 4);
#pragma unroll
            for (int mi = 0; mi < 2; mi++) {
                int r = wm * 32 + mi * 16 + (l & 15);
                ldm_x4(a[mi], sa + sw_off(r, cc));
            }
#pragma unroll
            for (int ni = 0; ni < 4; ni++) {
                int r = wn * 64 + ni * 16 + (l & 15);
                ldm_x4(b[ni], sbm + sw_off(r, cc));
            }
#pragma unroll
            for (int mi = 0; mi < 2; mi++)
#pragma unroll
                for (int ni = 0; ni < 4; ni++) {
                    mma16816(acc[mi][ni * 2],     a[mi], b[ni][0], b[ni][2]);
                    mma16816(acc[mi][ni * 2 + 1], a[mi], b[ni][1], b[ni][3]);
                }
        }
        buf = (buf + 1) % 3;
    }

    __syncthreads();

    if (qk) {
        __nv_bfloat16* sv = (__nv_bfloat16*)smem;    // [128][QSTRIDE]
#pragma unroll
        for (int mi = 0; mi < 2; mi++) {
            int rloc = wm * 32 + mi * 16 + (l >> 2);
#pragma unroll
            for (int ni = 0; ni < 8; ni++) {
                int cl = wn * 64 + ni * 8 + (l & 3) * 2;
                *(__nv_bfloat162*)(sv + rloc * QSTRIDE + cl) =
                    __halves2bfloat162(__float2bfloat16(acc[mi][ni][0]),
                                       __float2bfloat16(acc[mi][ni][1]));
                *(__nv_bfloat162*)(sv + (rloc + 8) * QSTRIDE + cl) =
                    __halves2bfloat162(__float2bfloat16(acc[mi][ni][2]),
                                       __float2bfloat16(acc[mi][ni][3]));
            }
        }
        __syncthreads();
        const int rr = tid >> 4;
        const int cc8 = (tid & 15) * 8;
#pragma unroll
        for (int it = 0; it < 8; it++) {
            int r = it * 16 + rr;
            *(uint4*)(g_Pbf + (row0 + r) * 512 + nloc + cc8) =
                *(const uint4*)(sv + r * QSTRIDE + cc8);
        }
    } else {
        __nv_bfloat16* sv = (__nv_bfloat16*)smem;    // [128][VSTRIDE]
#pragma unroll
        for (int mi = 0; mi < 2; mi++) {
            int rloc = wm * 32 + mi * 16 + (l >> 2);
#pragma unroll
            for (int ni = 0; ni < 8; ni++) {
                int fl = wn * 32 + ni * 4 + (l & 3);
                float ve0 = acc[mi][ni][0] / (1.f + __expf(-acc[mi][ni][1]));
                float ve1 = acc[mi][ni][2] / (1.f + __expf(-acc[mi][ni][3]));
                sv[rloc * VSTRIDE + fl]       = __float2bfloat16(ve0);
                sv[(rloc + 8) * VSTRIDE + fl] = __float2bfloat16(ve1);
            }
        }
        __syncthreads();
        const int rr = tid >> 3;
        const int cc8 = (tid & 7) * 8;
        const int fbase = nloc / 2;
#pragma unroll
        for (int it = 0; it < 4; it++) {
            int r = it * 32 + rr;
            *(uint4*)(g_Veff + (row0 + r) * 256 + fbase + cc8) =
                *(const uint4*)(sv + r * VSTRIDE + cc8);
        }
    }
}

// ============================================================================
// FUSED attention + GEMM2 + residual + LN.
// Phase A stages K/V_eff for BOTH samples per warp via cp.async (bf16,
// 72B head slots), reads back with 8B-aligned uint2 loads. Bit-identical math.
// Per-warp staging: 2 samples x [8 rows x 576B] = 9216 B.
// ============================================================================
#define SM_AHI 0
#define SM_STAGE 32768
#define G2F_SMEM (32768 + 73728)

__global__ void __launch_bounds__(256, 2)
k_attn_gemm2(const float* __restrict__ tok, const float* __restrict__ gma,
             const float* __restrict__ bta, float* __restrict__ Y,
             float* __restrict__ attn_out)
{
    extern __shared__ __align__(1024) char smem[];
    const uint32_t sb = smem_u32(smem);
    const int tid = threadIdx.x;
    const int l = tid & 31, w = tid >> 5;
    const size_t row0 = (size_t)blockIdx.x * 64;

    // ======================= Phase A: attention =============================
    {
        const uint32_t wbase = sb + SM_STAGE + w * 9216;
        const char* wptr = smem + SM_STAGE + w * 9216;
        const int i = l >> 3;
        const int h = l & 7;

        // ---- async staging of K and V_eff for both samples of this warp ----
#pragma unroll
        for (int j = 0; j < 32; j++) {
            const int smp = j >> 4;                 // 0..1
            const int r = (j >> 1) & 7;             // 0..7 (0-3: K, 4-7: V)
            const int ch = ((j & 1) << 5) + l;      // 0..63 (8B units in row)
            const size_t rowb = row0 + (size_t)(smp * 8 + w) * 4;
            const void* src = (r < 4)
                ? (const void*)(g_Pbf + (rowb + r) * 512 + 256 + ch * 4)
                : (const void*)(g_Veff + (rowb + (r - 4)) * 256 + ch * 4);
            uint32_t dst = wbase + smp * 4608 + r * 576 + (ch >> 3) * 72 + (ch & 7) * 8;
            cp8(dst, src);
        }
        cp_commit();
        cp_wait0();
        __syncwarp();

        // ---- compute both samples from SMEM ----
#pragma unroll
        for (int smp = 0; smp < 2; smp++) {
            const int sl = smp * 8 + w;
            const size_t rowb = row0 + (size_t)sl * 4;
            const size_t t = rowb + i;
            const char* sbase = wptr + smp * 4608;

            float4 Q[8];
            {
                const bf8* qp = (const bf8*)(g_Pbf + t * 512 + h * 32);
#pragma unroll
                for (int c = 0; c < 4; c++) {
                    bf8 qv = qp[c];
                    uint4 u = *(const uint4*)&qv;
                    bf8_unpack(u, Q[c * 2], Q[c * 2 + 1]);
                }
            }

            float s[3];
#pragma unroll
            for (int lix = 0; lix < 3; lix++) {
                int nb = (lix >= i) ? lix + 1 : lix;
                const char* kp = sbase + nb * 576 + h * 72;
                float a0 = 0.f, a1 = 0.f;
#pragma unroll
                for (int c = 0; c < 4; c++) {
                    float4 k0 = bf4_unpack(*(const uint2*)(kp + c * 16));
                    float4 k1 = bf4_unpack(*(const uint2*)(kp + c * 16 + 8));
                    float4 q0 = Q[c * 2], q1 = Q[c * 2 + 1];
                    a0 = fmaf(q0.x, k0.x, a0); a0 = fmaf(q0.y, k0.y, a0);
                    a0 = fmaf(q0.z, k0.z, a0); a0 = fmaf(q0.w, k0.w, a0);
                    a1 = fmaf(q1.x, k1.x, a1); a1 = fmaf(q1.y, k1.y, a1);
                    a1 = fmaf(q1.z, k1.z, a1); a1 = fmaf(q1.w, k1.w, a1);
                }
                s[lix] = (a0 + a1) * QK_SCALE;
            }

            float m = fmaxf(s[0], fmaxf(s[1], s[2]));
            float e0 = __expf(s[0] - m), e1 = __expf(s[1] - m), e2 = __expf(s[2] - m);
            float inv = 1.f / (e0 + e1 + e2);
            float a[3] = { e0 * inv, e1 * inv, e2 * inv };

            size_t ao = (t * 8 + h) * 3;
            attn_out[ao + 0] = a[0]; attn_out[ao + 1] = a[1]; attn_out[ao + 2] = a[2];

            float O[32];
#pragma unroll
            for (int d = 0; d < 32; d++) O[d] = 0.f;
#pragma unroll
            for (int lix = 0; lix < 3; lix++) {
                int nb = (lix >= i) ? lix + 1 : lix;
                const char* vp = sbase + (4 + nb) * 576 + h * 72;
                float al = a[lix];
#pragma unroll
                for (int c = 0; c < 4; c++) {
                    float4 v0 = bf4_unpack(*(const uint2*)(vp + c * 16));
                    float4 v1 = bf4_unpack(*(const uint2*)(vp + c * 16 + 8));
                    O[c*8+0] = fmaf(al, v0.x, O[c*8+0]);
                    O[c*8+1] = fmaf(al, v0.y, O[c*8+1]);
                    O[c*8+2] = fmaf(al, v0.z, O[c*8+2]);
                    O[c*8+3] = fmaf(al, v0.w, O[c*8+3]);
                    O[c*8+4] = fmaf(al, v1.x, O[c*8+4]);
                    O[c*8+5] = fmaf(al, v1.y, O[c*8+5]);
                    O[c*8+6] = fmaf(al, v1.z, O[c*8+6]);
                    O[c*8+7] = fmaf(al, v1.w, O[c*8+7]);
                }
            }

            const int arow = sl * 4 + i;
#pragma unroll
            for (int j = 0; j < 4; j++) {
                int col = h * 32 + j * 8;
                int kblk = col >> 6;
                int cw = (col & 63) >> 3;
                bf4 lo8 = to_bf4(make_float4(O[j*8+0], O[j*8+1], O[j*8+2], O[j*8+3]));
                bf4 hi8 = to_bf4(make_float4(O[j*8+4], O[j*8+5], O[j*8+6], O[j*8+7]));
                char* dst = smem + SM_AHI + kblk * 8192 + sw_off(arow, cw);
                *(bf4*)dst       = lo8;
                *(bf4*)(dst + 8) = hi8;
            }
        }
    }
    __syncthreads();

    // ======================= Phase B: Wo GEMM ===============================
    const int wm = w & 1, wn = w >> 1;
    const int lr = tid >> 3, lc = tid & 7;

    float acc[2][8][4];
#pragma unroll
    for (int i = 0; i < 2; i++)
#pragma unroll
        for (int j = 0; j < 8; j++)
#pragma unroll
            for (int k = 0; k < 4; k++) acc[i][j][k] = 0.f;

    auto issueB = [&](int s, int buf) {
        const int k0 = s * 64;
        const uint32_t sbm = sb + SM_STAGE + buf * 32768;
#pragma unroll
        for (int u = 0; u < 8; u++) {
            int r = lr + u * 32;
            cp16(sbm + sw_off(r, lc), g_Wo1 + (size_t)r * 256 + k0 + lc * 8);
        }
    };

    issueB(0, 0); cp_commit();

    for (int s = 0; s < 4; s++) {
        if (s + 1 < 4) issueB(s + 1, (s + 1) & 1);
        cp_commit();
        cp_wait1();
        __syncthreads();

        const uint32_t sa  = sb + SM_AHI + s * 8192;
        const uint32_t sbm = sb + SM_STAGE + (s & 1) * 32768;
#pragma unroll
        for (int ks = 0; ks < 4; ks++) {
            uint32_t a[2][4], b[4][4];
            const int cc = ks * 2 + (l >> 4);
#pragma unroll
            for (int mi = 0; mi < 2; mi++) {
                int r = wm * 32 + mi * 16 + (l & 15);
                ldm_x4(a[mi], sa + sw_off(r, cc));
            }
#pragma unroll
            for (int ni = 0; ni < 4; ni++) {
                int r = wn * 64 + ni * 16 + (l & 15);
                ldm_x4(b[ni], sbm + sw_off(r, cc));
            }
#pragma unroll
            for (int mi = 0; mi < 2; mi++)
#pragma unroll
                for (int ni = 0; ni < 4; ni++) {
                    mma16816(acc[mi][ni * 2],     a[mi], b[ni][0], b[ni][2]);
                    mma16816(acc[mi][ni * 2 + 1], a[mi], b[ni][1], b[ni][3]);
                }
        }
        __syncthreads();
    }

    // ======================= Phase C: residual + LN =========================
    float* sred = (float*)(smem + SM_STAGE);
#pragma unroll
    for (int mi = 0; mi < 2; mi++) {
        int rb = wm * 32 + mi * 16 + (l >> 2);
#pragma unroll
        for (int ni = 0; ni < 8; ni++) {
            int col = wn * 64 + ni * 8 + (l & 3) * 2;
            *(float2*)(sred + rb * 260 + col) = make_float2(acc[mi][ni][0], acc[mi][ni][1]);
            *(float2*)(sred + (rb + 8) * 260 + col) = make_float2(acc[mi][ni][2], acc[mi][ni][3]);
        }
    }
    __syncthreads();

#pragma unroll
    for (int rr = 0; rr < 8; rr++) {
        int row = w * 8 + rr;
        size_t grow = row0 + row;
        float v[8];
        float4 t0 = *(const float4*)(tok + grow * 256 + l * 8);
        float4 t1 = *(const float4*)(tok + grow * 256 + l * 8 + 4);
        float4 s0 = *(const float4*)(sred + row * 260 + l * 8);
        float4 s1 = *(const float4*)(sred + row * 260 + l * 8 + 4);
        v[0] = s0.x + t0.x; v[1] = s0.y + t0.y; v[2] = s0.z + t0.z; v[3] = s0.w + t0.w;
        v[4] = s1.x + t1.x; v[5] = s1.y + t1.y; v[6] = s1.z + t1.z; v[7] = s1.w + t1.w;

        float sum = 0.f, sq = 0.f;
#pragma unroll
        for (int u = 0; u < 8; u++) { sum += v[u]; sq += v[u] * v[u]; }
#pragma unroll
        for (int off = 16; off >= 1; off >>= 1) {
            sum += __shfl_xor_sync(0xffffffffu, sum, off);
            sq  += __shfl_xor_sync(0xffffffffu, sq, off);
        }
        float mu = sum * (1.f / 256.f);
        float var = sq * (1.f / 256.f) - mu * mu;
        float is = rsqrtf(var + 1e-5f);

        float4 g0 = *(const float4*)(gma + l * 8);
        float4 g1 = *(const float4*)(gma + l * 8 + 4);
        float4 b0 = *(const float4*)(bta + l * 8);
        float4 b1 = *(const float4*)(bta + l * 8 + 4);
        *(float4*)(Y + grow * 256 + l * 8) = make_float4(
            (v[0]-mu)*is*g0.x + b0.x, (v[1]-mu)*is*g0.y + b0.y,
            (v[2]-mu)*is*g0.z + b0.z, (v[3]-mu)*is*g0.w + b0.w);
        *(float4*)(Y + grow * 256 + l * 8 + 4) = make_float4(
            (v[4]-mu)*is*g1.x + b1.x, (v[5]-mu)*is*g1.y + b1.y,
            (v[6]-mu)*is*g1.z + b1.z, (v[7]-mu)*is*g1.w + b1.w);
    }
}

// ============================================================================
extern "C" void kernel_launch(void* const* d_in, const int* in_sizes, int n_in,
                              void* d_out, int out_size)
{
    const float* tokens = (const float*)d_in[0];
    const float* Wq = (const float*)d_in[1];
    const float* Wk = (const float*)d_in[2];
    const float* Wv = (const float*)d_in[3];
    const float* Wr = (const float*)d_in[4];
    const float* Wo = (const float*)d_in[5];
    const float* ln_g = (const float*)d_in[6];
    const float* ln_b = (const float*)d_in[7];

    float* y = (float*)d_out;
    float* attn = y + (size_t)NT * 256;

    static int configured = 0;
    if (!configured) {
        cudaFuncSetAttribute(k_gemm1, cudaFuncAttributeMaxDynamicSharedMemorySize, G1_SMEM);
        cudaFuncSetAttribute(k_attn_gemm2, cudaFuncAttributeMaxDynamicSharedMemorySize, G2F_SMEM);
        configured = 1;
    }

    k_convX<<<NT * 64 / 256, 256>>>(tokens);
    k_convW<<<1280 * 64 / 256, 256>>>(Wq, Wk, Wv, Wr, Wo);
    k_gemm1<<<dim3(8, 1024), 256, G1_SMEM>>>();
    k_attn_gemm2<<<NT / 64, 256, G2F_SMEM>>>(tokens, ln_g, ln_b, y, attn);
}